// round 2
// baseline (speedup 1.0000x reference)
#include <cuda_runtime.h>
#include <cstddef>

// ---------------------------------------------------------------------------
// Problem constants
// ---------------------------------------------------------------------------
#define HH 384
#define WW 384
#define BB 2
#define NFC 64
#define COUTF 35   // output conv channels (sum of SECTIONS = 2+3+4+5+6+7+8 = 35)

// Scratch activations (allocation-free rule: __device__ globals)
__device__ float g_bufA[(size_t)BB * NFC * HH * WW];
__device__ float g_bufB[(size_t)BB * NFC * HH * WW];
__device__ float g_core[(size_t)BB * COUTF * HH * WW];

// ---------------------------------------------------------------------------
// 3x3 SAME conv (cross-correlation, NCHW / OIHW), optional ReLU / residual add
// Block: 256 threads = 16 co-groups x 16 columns. Tile: 8 rows x 16 cols,
// all COUT channels. Per thread: CO_PER co x 8 rows. Input chunk (CB channels)
// staged in smem; weights chunk staged in smem.
// ---------------------------------------------------------------------------
template<int CIN, int CB, int COUT, int CO_PER, bool RELU, bool RESID>
__global__ __launch_bounds__(256)
void conv3x3(const float* __restrict__ in, const float* __restrict__ wgt,
             const float* __restrict__ bias, const float* __restrict__ res,
             float* __restrict__ out)
{
    __shared__ float sIn[CB][10][20];      // 10 rows x 18 cols used, pad to 20
    __shared__ float sW[CB][COUT][10];     // 9 taps, pad to 10

    const int t  = threadIdx.x;
    const int tp = t & 15;                 // column within tile
    const int tc = t >> 4;                 // co group (0..15)
    const int bx = blockIdx.x, by = blockIdx.y, b = blockIdx.z;
    const int x0 = bx * 16;
    const int y0 = by * 8;

    float acc[CO_PER][8];
    #pragma unroll
    for (int i = 0; i < CO_PER; ++i) {
        int co = tc * CO_PER + i;
        float bv = (co < COUT) ? bias[co] : 0.f;
        #pragma unroll
        for (int r = 0; r < 8; ++r) acc[i][r] = bv;
    }

    for (int cb = 0; cb < CIN; cb += CB) {
        __syncthreads();
        // --- stage input tile (CB x 10 x 18), zero-padded at borders ---
        const int NIN = CB * 10 * 18;
        for (int idx = t; idx < NIN; idx += 256) {
            int ci  = idx / 180;
            int rem = idx - ci * 180;
            int ry  = rem / 18;
            int cx  = rem - ry * 18;
            int gy  = y0 - 1 + ry;
            int gx  = x0 - 1 + cx;
            float v = 0.f;
            if (gy >= 0 && gy < HH && gx >= 0 && gx < WW)
                v = in[(((size_t)b * CIN + cb + ci) * HH + gy) * WW + gx];
            sIn[ci][ry][cx] = v;
        }
        // --- stage weights (CB x COUT x 9) ---
        const int NW = CB * COUT * 9;
        for (int idx = t; idx < NW; idx += 256) {
            int ci  = idx / (COUT * 9);
            int rem = idx - ci * (COUT * 9);
            int co  = rem / 9;
            int k   = rem - co * 9;
            sW[ci][co][k] = wgt[((size_t)co * CIN + cb + ci) * 9 + k];
        }
        __syncthreads();

        #pragma unroll 1
        for (int ci = 0; ci < CB; ++ci) {
            float xv[10][3];
            #pragma unroll
            for (int r = 0; r < 10; ++r)
                #pragma unroll
                for (int c = 0; c < 3; ++c)
                    xv[r][c] = sIn[ci][r][tp + c];
            #pragma unroll
            for (int i = 0; i < CO_PER; ++i) {
                int co = tc * CO_PER + i;
                if (CO_PER * 16 > COUT && co >= COUT) break;
                const float* wp = sW[ci][co];
                #pragma unroll
                for (int ky = 0; ky < 3; ++ky)
                    #pragma unroll
                    for (int kx = 0; kx < 3; ++kx) {
                        float w = wp[ky * 3 + kx];
                        #pragma unroll
                        for (int r = 0; r < 8; ++r)
                            acc[i][r] += w * xv[r + ky][kx];
                    }
            }
        }
    }

    #pragma unroll
    for (int i = 0; i < CO_PER; ++i) {
        int co = tc * CO_PER + i;
        if (CO_PER * 16 > COUT && co >= COUT) break;
        #pragma unroll
        for (int r = 0; r < 8; ++r) {
            size_t oi = (((size_t)b * COUT + co) * HH + (y0 + r)) * WW + (x0 + tp);
            float v = acc[i][r];
            if (RELU)  v = fmaxf(v, 0.f);
            if (RESID) v += res[oi];
            out[oi] = v;
        }
    }
}

// ---------------------------------------------------------------------------
// KPN aggregation. Radial interpolation tables are computed at COMPILE TIME
// (exact integer sqrt classification + constexpr Newton for fractional part),
// so all channel indices are immediates -> core channels live in registers.
// ---------------------------------------------------------------------------
#define FST 33   // frame tile smem stride (odd -> conflict friendly)
#define FTH 30   // frame tile extent: 16 + 2*7

struct TEnt { int lo, hi, doff; bool inR; float a, b; };

__host__ __device__ constexpr double csqrt_(double x) {
    double g = x > 1.0 ? x : 1.0;
    for (int i = 0; i < 100; ++i) g = 0.5 * (g + x / g);
    return g;
}

// Entry for section of half-width W (kernel K=2W-1), flat position P.
__host__ __device__ constexpr TEnt tentry(int w, int p) {
    const int K = 2 * w - 1;
    const int r = w - 1;
    const int coff = w * (w - 1) / 2 - 1;   // 0,2,5,9,14,20,27
    const int i = p / K, j = p % K;
    TEnt e{};
    e.doff = (i - r) * FST + (j - r);
    const int s2 = (i - r) * (i - r) + (j - r) * (j - r);
    // exact integer floor of sqrt(s2)
    int q = 0;
    while ((q + 1) * (q + 1) <= s2) ++q;
    if (q * q == s2) {                      // d is exactly integer q
        if (q > r) { e.inR = false; e.lo = coff; e.hi = coff; e.a = 0.f; e.b = 0.f; }
        else       { e.inR = true;  e.lo = coff + q; e.hi = coff + q; e.a = 1.f; e.b = 0.f; }
    } else {                                // q < d < q+1 strictly
        if (q >= r) { e.inR = false; e.lo = coff; e.hi = coff; e.a = 0.f; e.b = 0.f; }
        else {
            double d = csqrt_((double)s2);
            e.inR = true;
            e.lo = coff + q;
            e.hi = coff + q + 1;
            e.a = (float)((double)(q + 1) - d);
            e.b = (float)(d - (double)q);
        }
    }
    return e;
}

// Divide-and-conquer tap expansion: covers range [Lo, Lo+N). Recursion depth
// is O(log2 N) (~8 for N=225), avoiding nvcc's template depth limit.
template<int W, int Lo, int N>
struct KLoop {
    static __device__ __forceinline__ void run(const float (&c)[COUTF],
                                               const float* __restrict__ sF,
                                               int center, float& den, float& num) {
        KLoop<W, Lo, N / 2>::run(c, sF, center, den, num);
        KLoop<W, Lo + N / 2, N - N / 2>::run(c, sF, center, den, num);
    }
};

template<int W, int Lo>
struct KLoop<W, Lo, 1> {
    static __device__ __forceinline__ void run(const float (&c)[COUTF],
                                               const float* __restrict__ sF,
                                               int center, float& den, float& num) {
        constexpr TEnt e = tentry(W, Lo);
        float patch = sF[center + e.doff];
        if constexpr (e.inR) {
            float v = e.a * c[e.lo] + e.b * c[e.hi];
            float tt = __expf(v);
            den += tt;
            num += tt * patch;
        } else {
            den += 1.f;     // exp(0)
            num += patch;
        }
    }
};

template<int W, int Lo>
struct KLoop<W, Lo, 0> {
    static __device__ __forceinline__ void run(const float (&)[COUTF],
                                               const float* __restrict__,
                                               int, float&, float&) {}
};

template<int W>
__device__ __forceinline__ float section_run(const float (&c)[COUTF],
                                             const float* __restrict__ sF, int center) {
    constexpr int K = 2 * W - 1;
    float den = 0.f, num = 0.f;
    KLoop<W, 0, K * K>::run(c, sF, center, den, num);
    return num / den;
}

__global__ __launch_bounds__(256)
void kpn_kernel(const float* __restrict__ core, const float* __restrict__ data,
                float* __restrict__ out)
{
    __shared__ float sF[FTH * FST];
    const int t  = threadIdx.x;
    const int tx = t & 15, ty = t >> 4;
    const int bx = blockIdx.x, by = blockIdx.y, b = blockIdx.z;
    const int x  = bx * 16 + tx, y = by * 16 + ty;
    const int oy = by * 16 - 7,  ox = bx * 16 - 7;

    for (int idx = t; idx < FTH * FTH; idx += 256) {
        int fy = idx / FTH, fx = idx - fy * FTH;
        int gy = oy + fy,   gx = ox + fx;
        float v = 0.f;
        if (gy >= 0 && gy < HH && gx >= 0 && gx < WW)
            v = data[((size_t)b * HH + gy) * WW + gx];
        sF[fy * FST + fx] = v;
    }
    __syncthreads();

    float c[COUTF];
    #pragma unroll
    for (int ch = 0; ch < COUTF; ++ch)
        c[ch] = fabsf(core[(((size_t)b * COUTF + ch) * HH + y) * WW + x]);

    const int center = (ty + 7) * FST + (tx + 7);
    float pred = 0.f;
    pred += section_run<2>(c, sF, center);
    pred += section_run<3>(c, sF, center);
    pred += section_run<4>(c, sF, center);
    pred += section_run<5>(c, sF, center);
    pred += section_run<6>(c, sF, center);
    pred += section_run<7>(c, sF, center);
    pred += section_run<8>(c, sF, center);

    out[((size_t)b * HH + y) * WW + x] = pred;
}

// ---------------------------------------------------------------------------
// Launch
// ---------------------------------------------------------------------------
extern "C" void kernel_launch(void* const* d_in, const int* in_sizes, int n_in,
                              void* d_out, int out_size) {
    (void)in_sizes; (void)n_in; (void)out_size;
    const float* data_with_est = (const float*)d_in[0];
    const float* data    = (const float*)d_in[1];
    const float* w_first = (const float*)d_in[2];
    const float* b_first = (const float*)d_in[3];
    const float* w1a = (const float*)d_in[4];
    const float* b1a = (const float*)d_in[5];
    const float* w1b = (const float*)d_in[6];
    const float* b1b = (const float*)d_in[7];
    const float* w2a = (const float*)d_in[8];
    const float* b2a = (const float*)d_in[9];
    const float* w2b = (const float*)d_in[10];
    const float* b2b = (const float*)d_in[11];
    const float* w3a = (const float*)d_in[12];
    const float* b3a = (const float*)d_in[13];
    const float* w3b = (const float*)d_in[14];
    const float* b3b = (const float*)d_in[15];
    const float* w_out = (const float*)d_in[16];
    const float* b_out = (const float*)d_in[17];
    float* out = (float*)d_out;

    float *A = nullptr, *Bb = nullptr, *core = nullptr;
    cudaGetSymbolAddress((void**)&A, g_bufA);
    cudaGetSymbolAddress((void**)&Bb, g_bufB);
    cudaGetSymbolAddress((void**)&core, g_core);

    dim3 cgrid(WW / 16, HH / 8, BB), cblk(256);

    // first conv: 2 -> 64, no relu
    conv3x3<2, 2, NFC, 4, false, false><<<cgrid, cblk>>>(data_with_est, w_first, b_first, nullptr, A);
    // resblock 1
    conv3x3<NFC, 8, NFC, 4, true,  false><<<cgrid, cblk>>>(A,  w1a, b1a, nullptr, Bb);
    conv3x3<NFC, 8, NFC, 4, false, true ><<<cgrid, cblk>>>(Bb, w1b, b1b, A, A);
    // resblock 2
    conv3x3<NFC, 8, NFC, 4, true,  false><<<cgrid, cblk>>>(A,  w2a, b2a, nullptr, Bb);
    conv3x3<NFC, 8, NFC, 4, false, true ><<<cgrid, cblk>>>(Bb, w2b, b2b, A, A);
    // resblock 3
    conv3x3<NFC, 8, NFC, 4, true,  false><<<cgrid, cblk>>>(A,  w3a, b3a, nullptr, Bb);
    conv3x3<NFC, 8, NFC, 4, false, true ><<<cgrid, cblk>>>(Bb, w3b, b3b, A, A);
    // output conv: 64 -> 35
    conv3x3<NFC, 8, COUTF, 3, false, false><<<cgrid, cblk>>>(A, w_out, b_out, nullptr, core);

    // KPN aggregation
    kpn_kernel<<<dim3(WW / 16, HH / 16, BB), 256>>>(core, data, out);
}